// round 10
// baseline (speedup 1.0000x reference)
#include <cuda_runtime.h>
#include <cstdint>

// FP32->FP8(E4M3) bit-pulse converter.
// Input:  [N, 32] floats (0.0/1.0) = [S, E7..E0, M22..M0]  (IEEE order, MSB first)
// Output: [N, 8]  floats (0.0/1.0) = [S, E3..E0, M2..M0]
//
// Persistent grid-stride version: 1184 resident CTAs (8/SM x 148), each warp
// loops over 32-value tiles. Per tile:
//  Gather:  32 coalesced LDG.32 + 32 ballots; lane v keeps value v's IEEE word.
//  Convert: each lane converts exactly ONE value.
//  Store:   2 shfl + 2 coalesced STG.128 per lane.

__global__ __launch_bounds__(256)
void fp32_to_fp8_pulse_kernel(const uint32_t* __restrict__ in,
                              float* __restrict__ out,
                              int n_tiles)          // n_vals / 32 warp-tiles
{
    const int lane    = threadIdx.x & 31;
    const int warpIn  = threadIdx.x >> 5;           // 0..7
    const int nWarps  = (gridDim.x * blockDim.x) >> 5;
    int tile = blockIdx.x * 8 + warpIn;

    const int srcHi = lane >> 1;                    // store-phase shfl source
    const int nibSh = (lane & 1) ? 0 : 4;           // even lane: high nibble

    for (; tile < n_tiles; tile += nWarps) {
        const size_t vbase = (size_t)tile * 32;
        const uint32_t* inw = in + vbase * 32;

        // ---- gather: iteration v, lane l loads pulse l of value (vbase+v).
        // ballot bit l = pulse l; brev puts pulse 0 (sign) at bit 31.
        uint32_t myword = 0;
#pragma unroll
        for (int v = 0; v < 32; ++v) {
            uint32_t x = __ldcs(inw + v * 32 + lane);    // 0x0 or 0x3F800000
            unsigned m = __ballot_sync(0xFFFFFFFFu, x != 0u);
            if (v == lane) myword = m;
        }
        const uint32_t w = __brev(myword);

        // ---- convert this lane's single value ----
        uint32_t s    = w >> 31;
        uint32_t exp  = (w >> 23) & 0xFFu;
        uint32_t mant = w & 0x7FFFFFu;

        // normal path: exp8 = exp - 120, RNE 23 -> 3 mantissa bits
        uint32_t kept  = mant >> 20;
        uint32_t R     = (mant >> 19) & 1u;
        uint32_t S     = (mant & 0x7FFFFu) != 0u;
        uint32_t mr    = kept + (R & (S | (kept & 1u)));
        uint32_t carry = mr >> 3;
        uint32_t mant_norm = carry ? 0u : (mr & 7u);
        uint32_t exp_norm  = exp - 120u + carry;

        // subnormal path (117 <= exp <= 120): shift 1.mant right, RNE
        uint32_t full = 0x800000u | mant;
        int sh = 141 - (int)exp;
        sh = sh < 1 ? 1 : (sh > 24 ? 24 : sh);
        uint32_t kept_s = full >> sh;
        uint32_t Rs = (full >> (sh - 1)) & 1u;
        uint32_t Ss = (full & ((1u << (sh - 1)) - 1u)) != 0u;
        uint32_t ms = kept_s + (Rs & (Ss | (kept_s & 1u)));
        uint32_t sub_of   = ms >= 8u;
        uint32_t sub_exp  = sub_of ? 1u : 0u;
        uint32_t sub_mant = sub_of ? 0u : ms;

        // select overflow / subnormal / underflow / normal
        uint32_t exp8, mant8;
        if (exp > 134u)                      { exp8 = 15u;      mant8 = 6u; }
        else if (exp >= 117u && exp <= 120u) { exp8 = sub_exp;  mant8 = sub_mant; }
        else if (exp < 117u)                 { exp8 = 0u;       mant8 = 0u; }
        else                                 { exp8 = exp_norm; mant8 = mant_norm; }

        const uint32_t res = (s << 7) | (exp8 << 3) | mant8;  // bit7=S..bit0=M0

        // ---- store: 2 rounds of shfl + STG.128 ----
        // Round j, lane l writes outputs [128j+4l .. 128j+4l+3]: one nibble of
        // the res byte of value 16j + (l>>1).
        float4* o4 = (float4*)(out + vbase * 8);
#pragma unroll
        for (int j = 0; j < 2; ++j) {
            uint32_t r   = __shfl_sync(0xFFFFFFFFu, res, 16 * j + srcHi);
            uint32_t nib = (r >> nibSh) & 0xFu;
            float4 f;
            f.x = __uint_as_float(0x3F800000u & (0u - ((nib >> 3) & 1u)));
            f.y = __uint_as_float(0x3F800000u & (0u - ((nib >> 2) & 1u)));
            f.z = __uint_as_float(0x3F800000u & (0u - ((nib >> 1) & 1u)));
            f.w = __uint_as_float(0x3F800000u & (0u - (nib & 1u)));
            __stcs(o4 + j * 32 + lane, f);
        }
    }
}

extern "C" void kernel_launch(void* const* d_in, const int* in_sizes, int n_in,
                              void* d_out, int out_size)
{
    const uint32_t* in = (const uint32_t*)d_in[0];
    float* out = (float*)d_out;
    int n_vals  = in_sizes[0] / 32;          // 2,097,152
    int n_tiles = (n_vals + 31) / 32;        // 65,536 warp-tiles
    // Persistent grid: 8 CTAs/SM x 148 SMs = 1184 CTAs, 8 warps each.
    int blocks = 1184;
    fp32_to_fp8_pulse_kernel<<<blocks, 256>>>(in, out, n_tiles);
}

// round 12
// speedup vs baseline: 1.8546x; 1.8546x over previous
#include <cuda_runtime.h>
#include <cstdint>

// FP32->FP8(E4M3) bit-pulse converter.
// Input:  [N, 32] floats (0.0/1.0) = [S, E7..E0, M22..M0]  (IEEE order, MSB first)
// Output: [N, 8]  floats (0.0/1.0) = [S, E3..E0, M2..M0]
//
// One warp per 32 values (fixed grid — persistent variant regressed, MLP
// collapsed). Gather is split into explicit {16 LDG batch}->{16 ballots}
// phases so the LDG stream is decoupled from the VOTE dependency chain
// (high MLP). Each lane converts exactly one value; store via 2 shfl +
// 2 coalesced STG.128.

__global__ __launch_bounds__(256)
void fp32_to_fp8_pulse_kernel(const uint32_t* __restrict__ in,
                              float* __restrict__ out,
                              int n_vals)
{
    const int lane  = threadIdx.x & 31;
    const int warpG = (int)((blockIdx.x * blockDim.x + threadIdx.x) >> 5);
    const int vbase = warpG * 32;                 // first value this warp handles
    if (vbase >= n_vals) return;

    const uint32_t* inw = in + (size_t)vbase * 32;

    // ---- gather, phase-batched for MLP ----
    // Iteration v: lane l holds pulse l of value (vbase+v). Ballot bit l =
    // pulse l; brev puts pulse 0 (sign) at bit 31 -> IEEE fp32 word.
    uint32_t myword = 0;
    {
        uint32_t x[16];
#pragma unroll
        for (int v = 0; v < 16; ++v)              // 16 independent LDGs in flight
            x[v] = __ldcs(inw + v * 32 + lane);
#pragma unroll
        for (int v = 0; v < 16; ++v) {
            unsigned m = __ballot_sync(0xFFFFFFFFu, x[v] != 0u);
            if (v == lane) myword = m;
        }
#pragma unroll
        for (int v = 0; v < 16; ++v)              // second batch
            x[v] = __ldcs(inw + (16 + v) * 32 + lane);
#pragma unroll
        for (int v = 0; v < 16; ++v) {
            unsigned m = __ballot_sync(0xFFFFFFFFu, x[v] != 0u);
            if (16 + v == lane) myword = m;
        }
    }
    const uint32_t w = __brev(myword);

    // ---- convert this lane's single value ----
    uint32_t s    = w >> 31;
    uint32_t exp  = (w >> 23) & 0xFFu;
    uint32_t mant = w & 0x7FFFFFu;

    // normal path: exp8 = exp - 120, RNE 23 -> 3 mantissa bits
    uint32_t kept  = mant >> 20;
    uint32_t R     = (mant >> 19) & 1u;
    uint32_t S     = (mant & 0x7FFFFu) != 0u;
    uint32_t mr    = kept + (R & (S | (kept & 1u)));     // may carry into bit 3
    uint32_t carry = mr >> 3;
    uint32_t mant_norm = carry ? 0u : (mr & 7u);
    uint32_t exp_norm  = exp - 120u + carry;

    // subnormal path (117 <= exp <= 120): shift 1.mant right, RNE
    uint32_t full = 0x800000u | mant;                    // 24-bit 1.mant
    int sh = 141 - (int)exp;
    sh = sh < 1 ? 1 : (sh > 24 ? 24 : sh);
    uint32_t kept_s = full >> sh;
    uint32_t Rs = (full >> (sh - 1)) & 1u;
    uint32_t Ss = (full & ((1u << (sh - 1)) - 1u)) != 0u;
    uint32_t ms = kept_s + (Rs & (Ss | (kept_s & 1u)));
    uint32_t sub_of   = ms >= 8u;
    uint32_t sub_exp  = sub_of ? 1u : 0u;
    uint32_t sub_mant = sub_of ? 0u : ms;

    // select overflow / subnormal / underflow / normal
    uint32_t exp8, mant8;
    if (exp > 134u)                      { exp8 = 15u;      mant8 = 6u; }
    else if (exp >= 117u && exp <= 120u) { exp8 = sub_exp;  mant8 = sub_mant; }
    else if (exp < 117u)                 { exp8 = 0u;       mant8 = 0u; }
    else                                 { exp8 = exp_norm; mant8 = mant_norm; }

    const uint32_t res = (s << 7) | (exp8 << 3) | mant8; // bit7=S ... bit0=M0

    // ---- store: 2 rounds of shfl + STG.128 ----
    // Round j, lane l writes outputs [128j+4l .. 128j+4l+3]: one nibble of
    // the res byte of value 16j + (l>>1).
    float4* o4 = (float4*)(out + (size_t)vbase * 8);
    const int srcHi = lane >> 1;
    const int nibSh = (lane & 1) ? 0 : 4;                // even lane: high nibble

#pragma unroll
    for (int j = 0; j < 2; ++j) {
        uint32_t r   = __shfl_sync(0xFFFFFFFFu, res, 16 * j + srcHi);
        uint32_t nib = (r >> nibSh) & 0xFu;
        float4 f;
        f.x = __uint_as_float(0x3F800000u & (0u - ((nib >> 3) & 1u)));
        f.y = __uint_as_float(0x3F800000u & (0u - ((nib >> 2) & 1u)));
        f.z = __uint_as_float(0x3F800000u & (0u - ((nib >> 1) & 1u)));
        f.w = __uint_as_float(0x3F800000u & (0u - (nib & 1u)));
        __stcs(o4 + j * 32 + lane, f);
    }
}

extern "C" void kernel_launch(void* const* d_in, const int* in_sizes, int n_in,
                              void* d_out, int out_size)
{
    const uint32_t* in = (const uint32_t*)d_in[0];
    float* out = (float*)d_out;
    int n_vals = in_sizes[0] / 32;               // 2,097,152
    int warps  = (n_vals + 31) / 32;
    int blocks = (warps + 7) / 8;                // 256 threads = 8 warps/block
    fp32_to_fp8_pulse_kernel<<<blocks, 256>>>(in, out, n_vals);
}